// round 15
// baseline (speedup 1.0000x reference)
#include <cuda_runtime.h>
#include <cuda_fp16.h>
#include <cstdint>
#include <math.h>

// Problem constants
constexpr int Bn    = 4;
constexpr int Sn    = 4096;
constexpr int DIMn  = 1024;
constexpr int SDIMn = 256;
constexpr int Mn    = Bn * Sn;          // 16384 tokens
constexpr int TCH   = 16;               // scan chunk length
constexpr int NCH   = Sn / TCH;         // 256 chunks per sequence
constexpr int NBIG  = 2816;             // fused projection width

// fused projection column regions
constexpr int COL_G    = 1024;
constexpr int COL_XS   = 2048;
constexpr int COL_DEC  = 2304;
constexpr int COL_SEL  = 2560;

// ---------------- scratch (device globals; no allocations) ----------------
__device__ __align__(16) __half g_mixed[(size_t)Mn * DIMn];   // conv out (fp16)
__device__ __align__(16) __half g_u    [(size_t)Mn * DIMn];   // tanh(Wi)  fp16
__device__ __align__(16) __half g_gate [(size_t)Mn * DIMn];   // sig(Wg)   fp16
__device__ __align__(16) float  g_xs   [(size_t)Mn * SDIMn];  // tanh(Wsin) fp32
__device__ __align__(16) float  g_dec  [(size_t)Mn * SDIMn];  // sig(Wd)   fp32
__device__ __align__(16) __half g_sel  [(size_t)Mn * SDIMn];  // sig(Wsel) fp16
__device__ __align__(16) __half g_st   [(size_t)Mn * SDIMn];  // sel*state fp16
__device__ __align__(16) __half g_z    [(size_t)Mn * DIMn];   // gated z   fp16
__device__ __align__(16) float  g_chA  [Bn * NCH * SDIMn];
__device__ __align__(16) float  g_chB  [Bn * NCH * SDIMn];
__device__ __align__(16) float  g_chS0 [Bn * NCH * SDIMn];
__device__ __align__(16) float  g_bias [NBIG];

// transposed fp16 weights, packed [n][k] (element offsets)
constexpr size_t OFFB_WI   = 0;
constexpr size_t OFFB_WG   = (size_t)1024 * 1024;
constexpr size_t OFFB_WSIN = (size_t)2048 * 1024;
constexpr size_t OFFB_WD   = (size_t)2304 * 1024;
constexpr size_t OFFB_WSEL = (size_t)2560 * 1024;
constexpr size_t OFF_WSO   = (size_t)2816 * 1024;            // 1024 rows x K=256
constexpr size_t OFF_WOUT  = OFF_WSO + (size_t)1024 * 256;   // 1024 rows x K=1024
__device__ __align__(16) __half g_wT[OFF_WOUT + (size_t)1024 * 1024];

// ---------------- helpers ----------------
__device__ __forceinline__ uint32_t smem_u32(const void* p) {
    uint32_t a;
    asm("{ .reg .u64 t; cvta.to.shared.u64 t, %1; cvt.u32.u64 %0, t; }"
        : "=r"(a) : "l"(p));
    return a;
}
__device__ __forceinline__ void cpa16(uint32_t s, const void* g) {
    asm volatile("cp.async.cg.shared.global [%0], [%1], 16;" :: "r"(s), "l"(g));
}
__device__ __forceinline__ void ldsm4(uint32_t* r, uint32_t addr) {
    asm volatile("ldmatrix.sync.aligned.m8n8.x4.shared.b16 {%0,%1,%2,%3}, [%4];"
                 : "=r"(r[0]), "=r"(r[1]), "=r"(r[2]), "=r"(r[3]) : "r"(addr));
}
__device__ __forceinline__ void mma16(float* d, const uint32_t* a, const uint32_t* b) {
    asm volatile(
        "mma.sync.aligned.m16n8k16.row.col.f32.f16.f16.f32 "
        "{%0,%1,%2,%3}, {%4,%5,%6,%7}, {%8,%9}, {%0,%1,%2,%3};"
        : "+f"(d[0]), "+f"(d[1]), "+f"(d[2]), "+f"(d[3])
        : "r"(a[0]), "r"(a[1]), "r"(a[2]), "r"(a[3]), "r"(b[0]), "r"(b[1]));
}
// fast activations (used ONLY for fp16-stored outputs)
__device__ __forceinline__ float tanh_fast(float v) {
    float r; asm("tanh.approx.f32 %0, %1;" : "=f"(r) : "f"(v)); return r;
}
__device__ __forceinline__ float sig_fast(float v) {
    float t;
    asm("ex2.approx.f32 %0, %1;" : "=f"(t) : "f"(-v * 1.4426950408889634f));
    float r;
    asm("rcp.approx.f32 %0, %1;" : "=f"(r) : "f"(1.f + t));
    return r;
}

// ---------------- merged prep: LN+conv (blocks 0..1023) ----------------
//                  weight transposes (1024..5119), bias pack (5120..5130)
constexpr int LC_ROWS = 16;
constexpr int HROW    = DIMn + 8;    // halves per hbuf row
__global__ __launch_bounds__(256)
void prep_kernel(const float* __restrict__ x,
                 const float* __restrict__ gw, const float* __restrict__ bw,
                 const float* __restrict__ mw, const float* __restrict__ mb,
                 const float* __restrict__ Wi, const float* __restrict__ Wg,
                 const float* __restrict__ Wsin, const float* __restrict__ Wd,
                 const float* __restrict__ Wsel,
                 const float* __restrict__ Wso, const float* __restrict__ Wout,
                 const float* __restrict__ bi, const float* __restrict__ bg,
                 const float* __restrict__ bsin, const float* __restrict__ bd,
                 const float* __restrict__ bsel) {
    __shared__ __align__(16) char sbuf[(LC_ROWS + 2) * HROW * 2];  // 37152 B
    const int t = threadIdx.x;

    if (blockIdx.x < 1024) {
        // ---------- LN + conv ----------
        __half* hb = (__half*)sbuf;
        const int warp = t >> 5, lane = t & 31;
        const int m0 = blockIdx.x * LC_ROWS;
        const int s0 = m0 & (Sn - 1);

        for (int r = warp; r < LC_ROWS + 2; r += 8) {
            const int s = s0 - 1 + r;
            __half* row = hb + r * HROW;
            if (s < 0 || s >= Sn) {
                uint4 z = make_uint4(0u, 0u, 0u, 0u);
                uint4* rowp = (uint4*)row;
                #pragma unroll
                for (int i = 0; i < 4; i++) rowp[lane + 32 * i] = z;
                continue;
            }
            const int m = m0 - 1 + r;
            const float4* xr = (const float4*)(x + (size_t)m * DIMn);
            float4 v[8];
            float sm = 0.f, sm2 = 0.f;
            #pragma unroll
            for (int i = 0; i < 8; i++) {
                v[i] = xr[lane + 32 * i];
                sm  += v[i].x + v[i].y + v[i].z + v[i].w;
                sm2 += fmaf(v[i].x, v[i].x, fmaf(v[i].y, v[i].y,
                        fmaf(v[i].z, v[i].z, v[i].w * v[i].w)));
            }
            #pragma unroll
            for (int o = 16; o > 0; o >>= 1) {
                sm  += __shfl_xor_sync(0xffffffffu, sm,  o);
                sm2 += __shfl_xor_sync(0xffffffffu, sm2, o);
            }
            const float mu = sm * (1.0f / DIMn);
            const float rs = rsqrtf(sm2 * (1.0f / DIMn) - mu * mu + 1e-5f);
            #pragma unroll
            for (int i = 0; i < 8; i++) {
                const int c4 = lane + 32 * i;
                const float4 g4 = ((const float4*)gw)[c4];
                const float4 b4 = ((const float4*)bw)[c4];
                const float o0 = (v[i].x - mu) * rs * g4.x + b4.x;
                const float o1 = (v[i].y - mu) * rs * g4.y + b4.y;
                const float o2 = (v[i].z - mu) * rs * g4.z + b4.z;
                const float o3 = (v[i].w - mu) * rs * g4.w + b4.w;
                __half2* hp = (__half2*)row + c4 * 2;
                hp[0] = __floats2half2_rn(o0, o1);
                hp[1] = __floats2half2_rn(o2, o3);
            }
        }
        __syncthreads();

        const int c0 = t * 4;
        float w0[4], w1[4], w2[4], bb[4];
        #pragma unroll
        for (int j = 0; j < 4; j++) {
            w0[j] = __ldg(mw + (c0 + j) * 3 + 0);
            w1[j] = __ldg(mw + (c0 + j) * 3 + 1);
            w2[j] = __ldg(mw + (c0 + j) * 3 + 2);
            bb[j] = __ldg(mb + c0 + j);
        }
        for (int r = 0; r < LC_ROWS; r++) {
            const int m = m0 + r;
            float oc[4];
            #pragma unroll
            for (int j = 0; j < 4; j++) {
                const float lv = __half2float(hb[r * HROW + c0 + j]);
                const float cv = __half2float(hb[(r + 1) * HROW + c0 + j]);
                const float rv = __half2float(hb[(r + 2) * HROW + c0 + j]);
                oc[j] = fmaf(w0[j], lv, fmaf(w1[j], cv, fmaf(w2[j], rv, bb[j])));
            }
            __half2* dst = (__half2*)(g_mixed + (size_t)m * DIMn + c0);
            dst[0] = __floats2half2_rn(oc[0], oc[1]);
            dst[1] = __floats2half2_rn(oc[2], oc[3]);
        }
        return;
    }

    int bid = blockIdx.x - 1024;
    if (bid >= 4096) {
        // ---------- bias pack ----------
        const int i = (bid - 4096) * 256 + t;
        if (i < NBIG) {
            float v;
            if (i < 1024)      v = bi[i];
            else if (i < 2048) v = bg[i - 1024];
            else if (i < 2304) v = bsin[i - 2048];
            else if (i < 2560) v = bd[i - 2304];
            else               v = bsel[i - 2560];
            g_bias[i] = v;
        }
        return;
    }

    // ---------- weight transpose ----------
    float (*tile)[33] = (float(*)[33])sbuf;   // 32x33 floats = 4224 B
    const float* src; __half* dst; int N, Kd;
    if (bid < 1024)      { src = Wi;   dst = g_wT + OFFB_WI;   N = 1024; Kd = 1024; }
    else if (bid < 2048) { src = Wg;   dst = g_wT + OFFB_WG;   N = 1024; Kd = 1024; bid -= 1024; }
    else if (bid < 2304) { src = Wsin; dst = g_wT + OFFB_WSIN; N = 256;  Kd = 1024; bid -= 2048; }
    else if (bid < 2560) { src = Wd;   dst = g_wT + OFFB_WD;   N = 256;  Kd = 1024; bid -= 2304; }
    else if (bid < 2816) { src = Wsel; dst = g_wT + OFFB_WSEL; N = 256;  Kd = 1024; bid -= 2560; }
    else if (bid < 3072) { src = Wso;  dst = g_wT + OFF_WSO;   N = 1024; Kd = 256;  bid -= 2816; }
    else                 { src = Wout; dst = g_wT + OFF_WOUT;  N = 1024; Kd = 1024; bid -= 3072; }
    const int ntx = N / 32;
    const int n0 = (bid % ntx) * 32, k0 = (bid / ntx) * 32;
    const int tx = t & 31, ty = t >> 5;
    #pragma unroll
    for (int j = 0; j < 32; j += 8)
        tile[ty + j][tx] = src[(size_t)(k0 + ty + j) * N + n0 + tx];
    __syncthreads();
    #pragma unroll
    for (int j = 0; j < 32; j += 8)
        dst[(size_t)(n0 + ty + j) * Kd + k0 + tx] = __float2half_rn(tile[tx][ty + j]);
}

// ---------------- chunked scan, float2-vectorized, TCH=16 -----------------
__global__ void scan_p1() {
    const int b = blockIdx.y, c = blockIdx.x, n = threadIdx.x * 2;
    const size_t base = (size_t)(b * Sn + c * TCH) * SDIMn + n;
    float2 A = make_float2(1.f, 1.f), st = make_float2(0.f, 0.f);
    #pragma unroll
    for (int t = 0; t < TCH; t++) {
        const float2 d  = *(const float2*)(g_dec + base + (size_t)t * SDIMn);
        const float2 xv = *(const float2*)(g_xs  + base + (size_t)t * SDIMn);
        A.x *= d.x; A.y *= d.y;
        st.x = fmaf(d.x, st.x, (1.f - d.x) * xv.x);
        st.y = fmaf(d.y, st.y, (1.f - d.y) * xv.y);
    }
    const int o = (b * NCH + c) * SDIMn + n;
    *(float2*)(g_chA + o) = A;
    *(float2*)(g_chB + o) = st;
}
__global__ void scan_p2() {
    const int b = blockIdx.x, n = threadIdx.x * 2;
    float2 s = make_float2(0.f, 0.f);
    #pragma unroll 4
    for (int c = 0; c < NCH; c++) {
        const int o = (b * NCH + c) * SDIMn + n;
        *(float2*)(g_chS0 + o) = s;
        const float2 a = *(const float2*)(g_chA + o);
        const float2 bb = *(const float2*)(g_chB + o);
        s.x = fmaf(a.x, s.x, bb.x);
        s.y = fmaf(a.y, s.y, bb.y);
    }
}
__global__ void scan_p3() {
    const int b = blockIdx.y, c = blockIdx.x, n = threadIdx.x * 2;
    const size_t base = (size_t)(b * Sn + c * TCH) * SDIMn + n;
    float2 st = *(const float2*)(g_chS0 + (b * NCH + c) * SDIMn + n);
    #pragma unroll
    for (int t = 0; t < TCH; t++) {
        const float2 d  = *(const float2*)(g_dec + base + (size_t)t * SDIMn);
        const float2 xv = *(const float2*)(g_xs  + base + (size_t)t * SDIMn);
        st.x = fmaf(d.x, st.x, (1.f - d.x) * xv.x);
        st.y = fmaf(d.y, st.y, (1.f - d.y) * xv.y);
        const __half2 sl = *(const __half2*)(g_sel + base + (size_t)t * SDIMn);
        *(__half2*)(g_st + base + (size_t)t * SDIMn) =
            __floats2half2_rn(__low2float(sl) * st.x, __high2float(sl) * st.y);
    }
}

// ---------------- fp16 mma GEMM: 128x128 tile, K-chunk 64, 3-stage ring ---
constexpr int HPAD   = 72;                    // halves per smem row (64 + 8 pad)
constexpr int ROWB   = HPAD * 2;              // 144 bytes
constexpr int SROWS  = 256;                   // A rows 0-127, B rows 128-255
constexpr int STG_B  = SROWS * ROWB;          // 36864 B
constexpr int STAGES = 3;
constexpr int GSMEM  = STAGES * STG_B;        // 110592 B per CTA

template <int EPI, int K>
__global__ void __launch_bounds__(256, 2)
mma3(const __half* __restrict__ A, const __half* __restrict__ Bt,
     const float* __restrict__ bias, void* __restrict__ Cv,
     const void* __restrict__ e1, const void* __restrict__ e2,
     int ldc, int lde) {
    extern __shared__ __half smh[];
    const int tid  = threadIdx.x;
    const int wid  = tid >> 5, lane = tid & 31;
    const int wm   = wid & 1;        // 2 row groups of 64
    const int wn   = wid >> 1;       // 4 col groups of 32
    const int bm   = blockIdx.y * 128;
    const int bn   = blockIdx.x * 128;
    const uint32_t base = smem_u32(smh);
    uint32_t sbase[STAGES];
    #pragma unroll
    for (int s = 0; s < STAGES; s++) sbase[s] = base + (uint32_t)(s * STG_B);

    const int r0 = tid >> 3;
    const int q  = tid & 7;
    const __half* nA = A  + (size_t)(bm + r0) * K + q * 8;
    const __half* nB = Bt + (size_t)(bn + r0) * K + q * 8;
    uint32_t swoff[8];
    #pragma unroll
    for (int i = 0; i < 8; i++)
        swoff[i] = (uint32_t)((i * 32 + r0) * ROWB + q * 16);

    auto stage = [&](int buf) {
        const uint32_t sb = sbase[buf];
        #pragma unroll
        for (int i = 0; i < 4; i++)
            cpa16(sb + swoff[i], nA + (size_t)i * 32 * K);
        #pragma unroll
        for (int i = 0; i < 4; i++)
            cpa16(sb + swoff[4 + i], nB + (size_t)i * 32 * K);
        asm volatile("cp.async.commit_group;" ::: "memory");
        nA += 64; nB += 64;
    };

    uint32_t offA[4], offB[2];
    {
        const int blk = lane >> 3, rIn = lane & 7;
        #pragma unroll
        for (int i = 0; i < 4; i++) {
            const int row = wm * 64 + 16 * i + (blk & 1) * 8 + rIn;
            const int kh  = (blk >> 1) * 8;
            offA[i] = (uint32_t)(row * ROWB + kh * 2);
        }
        #pragma unroll
        for (int p = 0; p < 2; p++) {
            const int row = 128 + wn * 32 + 16 * p + (blk >> 1) * 8 + rIn;
            const int kh  = (blk & 1) * 8;
            offB[p] = (uint32_t)(row * ROWB + kh * 2);
        }
    }

    float acc[4][4][4];
    #pragma unroll
    for (int i = 0; i < 4; i++)
        #pragma unroll
        for (int j = 0; j < 4; j++)
            #pragma unroll
            for (int qq = 0; qq < 4; qq++) acc[i][j][qq] = 0.f;

    constexpr int NKS = K / 64;
    static_assert(NKS >= 2, "K too small");

    stage(0);
    stage(1);

    int buf = 0;
    for (int ks = 0; ks < NKS; ks++) {
        asm volatile("cp.async.wait_group %0;" :: "n"(STAGES - 2) : "memory");
        __syncthreads();

        if (ks + STAGES - 1 < NKS) {
            int slot = buf + (STAGES - 1);
            if (slot >= STAGES) slot -= STAGES;
            stage(slot);
        } else {
            asm volatile("cp.async.commit_group;" ::: "memory");
        }

        const uint32_t sb = sbase[buf];
        #pragma unroll
        for (int k0 = 0; k0 < 4; k0++) {
            const uint32_t kb = sb + (uint32_t)(k0 * 32);
            uint32_t afr[4][4], bfr[4][2];
            #pragma unroll
            for (int i = 0; i < 4; i++) ldsm4(afr[i], kb + offA[i]);
            #pragma unroll
            for (int p = 0; p < 2; p++) {
                uint32_t r[4];
                ldsm4(r, kb + offB[p]);
                bfr[2 * p][0] = r[0];     bfr[2 * p][1] = r[1];
                bfr[2 * p + 1][0] = r[2]; bfr[2 * p + 1][1] = r[3];
            }
            #pragma unroll
            for (int i = 0; i < 4; i++)
                #pragma unroll
                for (int j = 0; j < 4; j++)
                    mma16(acc[i][j], afr[i], bfr[j]);
        }
        if (++buf == STAGES) buf = 0;
    }

    // ---- epilogue ----
    __half* dsth = nullptr; float* dstf = nullptr;
    int ldd = 0, cbase = 0;
    bool useTanh = false;
    if (EPI == 0) {
        if (bn < COL_G)        { dsth = g_u;    ldd = 1024;  cbase = 0;       useTanh = true;  }
        else if (bn < COL_XS)  { dsth = g_gate; ldd = 1024;  cbase = COL_G;   useTanh = false; }
        else if (bn < COL_DEC) { dstf = g_xs;   ldd = SDIMn; cbase = COL_XS;  useTanh = true;  }
        else if (bn < COL_SEL) { dstf = g_dec;  ldd = SDIMn; cbase = COL_DEC; useTanh = false; }
        else                   { dsth = g_sel;  ldd = SDIMn; cbase = COL_SEL; useTanh = false; }
    }
    const int g  = lane >> 2, tg = lane & 3;
    #pragma unroll
    for (int i = 0; i < 4; i++) {
        const int rr0 = bm + wm * 64 + 16 * i + g;
        #pragma unroll
        for (int j = 0; j < 4; j++) {
            const int col = bn + wn * 32 + 8 * j + 2 * tg;
            const float2 bs = *(const float2*)(bias + col);
            #pragma unroll
            for (int h = 0; h < 2; h++) {
                const int row = rr0 + 8 * h;
                const float v0 = acc[i][j][2 * h]     + bs.x;
                const float v1 = acc[i][j][2 * h + 1] + bs.y;
                if (EPI == 0) {
                    const int cl = col - cbase;
                    if (dsth) {
                        // fp16-stored: fast approx activations
                        float a0, a1;
                        if (useTanh) { a0 = tanh_fast(v0); a1 = tanh_fast(v1); }
                        else         { a0 = sig_fast(v0);  a1 = sig_fast(v1);  }
                        *(__half2*)(dsth + (size_t)row * ldd + cl) =
                            __floats2half2_rn(a0, a1);
                    } else {
                        // fp32-stored (feeds the scan): exact activations
                        float a0, a1;
                        if (useTanh) { a0 = tanhf(v0); a1 = tanhf(v1); }
                        else {
                            a0 = 1.f / (1.f + expf(-v0));
                            a1 = 1.f / (1.f + expf(-v1));
                        }
                        float2 o; o.x = a0; o.y = a1;
                        *(float2*)(dstf + (size_t)row * ldd + cl) = o;
                    }
                } else if (EPI == 1) {
                    const __half2 gg2 = *(const __half2*)((const __half*)e1 +
                                          (size_t)row * lde + col);
                    const __half2 uu2 = *(const __half2*)((const __half*)e2 +
                                          (size_t)row * lde + col);
                    const float gx = __low2float(gg2), gy = __high2float(gg2);
                    const float ux = __low2float(uu2), uy = __high2float(uu2);
                    const float z0 = gx * v0 + (1.f - gx) * ux;
                    const float z1 = gy * v1 + (1.f - gy) * uy;
                    *(__half2*)((__half*)Cv + (size_t)row * ldc + col) =
                        __floats2half2_rn(z0, z1);
                } else {
                    const float2 xx = *(const float2*)((const float*)e1 +
                                        (size_t)row * lde + col);
                    float2 o;
                    o.x = v0 + xx.x;
                    o.y = v1 + xx.y;
                    *(float2*)((float*)Cv + (size_t)row * ldc + col) = o;
                }
            }
        }
    }
}

// ---------------- launcher ----------------
extern "C" void kernel_launch(void* const* d_in, const int* in_sizes, int n_in,
                              void* d_out, int out_size) {
    const float* x    = (const float*)d_in[0];
    const float* ln_g = (const float*)d_in[1];
    const float* ln_b = (const float*)d_in[2];
    const float* mixw = (const float*)d_in[3];
    const float* mixb = (const float*)d_in[4];
    const float* Wi   = (const float*)d_in[5];
    const float* bi   = (const float*)d_in[6];
    const float* Wsin = (const float*)d_in[7];
    const float* bsin = (const float*)d_in[8];
    const float* Wd   = (const float*)d_in[9];
    const float* bd   = (const float*)d_in[10];
    const float* Wsel = (const float*)d_in[11];
    const float* bsel = (const float*)d_in[12];
    const float* Wso  = (const float*)d_in[13];
    const float* bso  = (const float*)d_in[14];
    const float* Wg   = (const float*)d_in[15];
    const float* bg   = (const float*)d_in[16];
    const float* Wout = (const float*)d_in[17];
    const float* bout = (const float*)d_in[18];

    float *p_bias;
    __half *p_mixed, *p_st, *p_z, *p_wT, *p_gate, *p_u;
    cudaGetSymbolAddress((void**)&p_mixed, g_mixed);
    cudaGetSymbolAddress((void**)&p_st,    g_st);
    cudaGetSymbolAddress((void**)&p_z,     g_z);
    cudaGetSymbolAddress((void**)&p_wT,    g_wT);
    cudaGetSymbolAddress((void**)&p_bias,  g_bias);
    cudaGetSymbolAddress((void**)&p_gate,  g_gate);
    cudaGetSymbolAddress((void**)&p_u,     g_u);

    cudaFuncSetAttribute((const void*)mma3<0, 1024>,
                         cudaFuncAttributeMaxDynamicSharedMemorySize, GSMEM);
    cudaFuncSetAttribute((const void*)mma3<1, 256>,
                         cudaFuncAttributeMaxDynamicSharedMemorySize, GSMEM);
    cudaFuncSetAttribute((const void*)mma3<2, 1024>,
                         cudaFuncAttributeMaxDynamicSharedMemorySize, GSMEM);

    // launch 0: merged LN+conv / transposes / bias pack
    prep_kernel<<<1024 + 4096 + 11, 256>>>(
        x, ln_g, ln_b, mixw, mixb,
        Wi, Wg, Wsin, Wd, Wsel, Wso, Wout,
        bi, bg, bsin, bd, bsel);

    // launch 1: fused projection GEMM -> split activation buffers
    mma3<0, 1024><<<dim3(NBIG / 128, Mn / 128), 256, GSMEM>>>(
        p_mixed, p_wT, p_bias, nullptr, nullptr, nullptr, 0, 0);

    // launch 2-4: chunked scan (TCH=16); p3 writes half(sel*state)
    scan_p1<<<dim3(NCH, Bn), 128>>>();
    scan_p2<<<Bn, 128>>>();
    scan_p3<<<dim3(NCH, Bn), 128>>>();

    // launch 5: y = (sel*st)@Wso + bso, fused gate -> z (fp16)
    mma3<1, 256><<<dim3(DIMn / 128, Mn / 128), 256, GSMEM>>>(
        p_st, p_wT + OFF_WSO, bso, p_z, p_gate, p_u, DIMn, DIMn);

    // launch 6: out = z@Wout + bout + x
    mma3<2, 1024><<<dim3(DIMn / 128, Mn / 128), 256, GSMEM>>>(
        p_z, p_wT + OFF_WOUT, bout, d_out, x, nullptr, DIMn, DIMn);
}

// round 17
// speedup vs baseline: 1.0549x; 1.0549x over previous
#include <cuda_runtime.h>
#include <cuda_fp16.h>
#include <cstdint>
#include <math.h>

// Problem constants
constexpr int Bn    = 4;
constexpr int Sn    = 4096;
constexpr int DIMn  = 1024;
constexpr int SDIMn = 256;
constexpr int Mn    = Bn * Sn;          // 16384 tokens
constexpr int TCH   = 32;               // scan chunk length
constexpr int NCH   = Sn / TCH;         // 128 chunks per sequence
constexpr int NBIG  = 2816;             // fused projection width

// fused projection column regions
constexpr int COL_G    = 1024;
constexpr int COL_XS   = 2048;
constexpr int COL_DEC  = 2304;
constexpr int COL_SEL  = 2560;

// ---------------- scratch (device globals; no allocations) ----------------
__device__ __align__(16) __half g_mixed[(size_t)Mn * DIMn];   // conv out (fp16)
__device__ __align__(16) __half g_u    [(size_t)Mn * DIMn];   // tanh(Wi)  fp16
__device__ __align__(16) __half g_gate [(size_t)Mn * DIMn];   // sig(Wg)   fp16
__device__ __align__(16) float  g_xs   [(size_t)Mn * SDIMn];  // tanh(Wsin) fp32
__device__ __align__(16) float  g_dec  [(size_t)Mn * SDIMn];  // sig(Wd)   fp32
__device__ __align__(16) __half g_sel  [(size_t)Mn * SDIMn];  // sig(Wsel) fp16
__device__ __align__(16) __half g_st   [(size_t)Mn * SDIMn];  // sel*state fp16
__device__ __align__(16) __half g_z    [(size_t)Mn * DIMn];   // gated z   fp16
__device__ __align__(16) float  g_chA  [Bn * NCH * SDIMn];
__device__ __align__(16) float  g_chB  [Bn * NCH * SDIMn];
__device__ __align__(16) float  g_chS0 [Bn * NCH * SDIMn];
__device__ __align__(16) float  g_bias [NBIG];

// transposed fp16 weights, packed [n][k] (element offsets)
constexpr size_t OFFB_WI   = 0;
constexpr size_t OFFB_WG   = (size_t)1024 * 1024;
constexpr size_t OFFB_WSIN = (size_t)2048 * 1024;
constexpr size_t OFFB_WD   = (size_t)2304 * 1024;
constexpr size_t OFFB_WSEL = (size_t)2560 * 1024;
constexpr size_t OFF_WSO   = (size_t)2816 * 1024;            // 1024 rows x K=256
constexpr size_t OFF_WOUT  = OFF_WSO + (size_t)1024 * 256;   // 1024 rows x K=1024
__device__ __align__(16) __half g_wT[OFF_WOUT + (size_t)1024 * 1024];

// ---------------- helpers ----------------
__device__ __forceinline__ uint32_t smem_u32(const void* p) {
    uint32_t a;
    asm("{ .reg .u64 t; cvta.to.shared.u64 t, %1; cvt.u32.u64 %0, t; }"
        : "=r"(a) : "l"(p));
    return a;
}
__device__ __forceinline__ void cpa16(uint32_t s, const void* g) {
    asm volatile("cp.async.cg.shared.global [%0], [%1], 16;" :: "r"(s), "l"(g));
}
__device__ __forceinline__ void ldsm4(uint32_t* r, uint32_t addr) {
    asm volatile("ldmatrix.sync.aligned.m8n8.x4.shared.b16 {%0,%1,%2,%3}, [%4];"
                 : "=r"(r[0]), "=r"(r[1]), "=r"(r[2]), "=r"(r[3]) : "r"(addr));
}
__device__ __forceinline__ void mma16(float* d, const uint32_t* a, const uint32_t* b) {
    asm volatile(
        "mma.sync.aligned.m16n8k16.row.col.f32.f16.f16.f32 "
        "{%0,%1,%2,%3}, {%4,%5,%6,%7}, {%8,%9}, {%0,%1,%2,%3};"
        : "+f"(d[0]), "+f"(d[1]), "+f"(d[2]), "+f"(d[3])
        : "r"(a[0]), "r"(a[1]), "r"(a[2]), "r"(a[3]), "r"(b[0]), "r"(b[1]));
}
// fast activations (used ONLY for fp16-stored outputs)
__device__ __forceinline__ float tanh_fast(float v) {
    float r; asm("tanh.approx.f32 %0, %1;" : "=f"(r) : "f"(v)); return r;
}
__device__ __forceinline__ float sig_fast(float v) {
    float t;
    asm("ex2.approx.f32 %0, %1;" : "=f"(t) : "f"(-v * 1.4426950408889634f));
    float r;
    asm("rcp.approx.f32 %0, %1;" : "=f"(r) : "f"(1.f + t));
    return r;
}

// ---------------- merged prep: LN+conv (blocks 0..1023) ----------------
//                  weight transposes (1024..5119), bias pack (5120..5130)
constexpr int LC_ROWS = 16;
constexpr int HROW    = DIMn + 8;    // halves per hbuf row
__global__ __launch_bounds__(256)
void prep_kernel(const float* __restrict__ x,
                 const float* __restrict__ gw, const float* __restrict__ bw,
                 const float* __restrict__ mw, const float* __restrict__ mb,
                 const float* __restrict__ Wi, const float* __restrict__ Wg,
                 const float* __restrict__ Wsin, const float* __restrict__ Wd,
                 const float* __restrict__ Wsel,
                 const float* __restrict__ Wso, const float* __restrict__ Wout,
                 const float* __restrict__ bi, const float* __restrict__ bg,
                 const float* __restrict__ bsin, const float* __restrict__ bd,
                 const float* __restrict__ bsel) {
    __shared__ __align__(16) char sbuf[(LC_ROWS + 2) * HROW * 2];  // 37152 B
    const int t = threadIdx.x;

    if (blockIdx.x < 1024) {
        // ---------- LN + conv ----------
        __half* hb = (__half*)sbuf;
        const int warp = t >> 5, lane = t & 31;
        const int m0 = blockIdx.x * LC_ROWS;
        const int s0 = m0 & (Sn - 1);

        for (int r = warp; r < LC_ROWS + 2; r += 8) {
            const int s = s0 - 1 + r;
            __half* row = hb + r * HROW;
            if (s < 0 || s >= Sn) {
                uint4 z = make_uint4(0u, 0u, 0u, 0u);
                uint4* rowp = (uint4*)row;
                #pragma unroll
                for (int i = 0; i < 4; i++) rowp[lane + 32 * i] = z;
                continue;
            }
            const int m = m0 - 1 + r;
            const float4* xr = (const float4*)(x + (size_t)m * DIMn);
            float4 v[8];
            float sm = 0.f, sm2 = 0.f;
            #pragma unroll
            for (int i = 0; i < 8; i++) {
                v[i] = xr[lane + 32 * i];
                sm  += v[i].x + v[i].y + v[i].z + v[i].w;
                sm2 += fmaf(v[i].x, v[i].x, fmaf(v[i].y, v[i].y,
                        fmaf(v[i].z, v[i].z, v[i].w * v[i].w)));
            }
            #pragma unroll
            for (int o = 16; o > 0; o >>= 1) {
                sm  += __shfl_xor_sync(0xffffffffu, sm,  o);
                sm2 += __shfl_xor_sync(0xffffffffu, sm2, o);
            }
            const float mu = sm * (1.0f / DIMn);
            const float rs = rsqrtf(sm2 * (1.0f / DIMn) - mu * mu + 1e-5f);
            #pragma unroll
            for (int i = 0; i < 8; i++) {
                const int c4 = lane + 32 * i;
                const float4 g4 = ((const float4*)gw)[c4];
                const float4 b4 = ((const float4*)bw)[c4];
                const float o0 = (v[i].x - mu) * rs * g4.x + b4.x;
                const float o1 = (v[i].y - mu) * rs * g4.y + b4.y;
                const float o2 = (v[i].z - mu) * rs * g4.z + b4.z;
                const float o3 = (v[i].w - mu) * rs * g4.w + b4.w;
                __half2* hp = (__half2*)row + c4 * 2;
                hp[0] = __floats2half2_rn(o0, o1);
                hp[1] = __floats2half2_rn(o2, o3);
            }
        }
        __syncthreads();

        const int c0 = t * 4;
        float w0[4], w1[4], w2[4], bb[4];
        #pragma unroll
        for (int j = 0; j < 4; j++) {
            w0[j] = __ldg(mw + (c0 + j) * 3 + 0);
            w1[j] = __ldg(mw + (c0 + j) * 3 + 1);
            w2[j] = __ldg(mw + (c0 + j) * 3 + 2);
            bb[j] = __ldg(mb + c0 + j);
        }
        for (int r = 0; r < LC_ROWS; r++) {
            const int m = m0 + r;
            float oc[4];
            #pragma unroll
            for (int j = 0; j < 4; j++) {
                const float lv = __half2float(hb[r * HROW + c0 + j]);
                const float cv = __half2float(hb[(r + 1) * HROW + c0 + j]);
                const float rv = __half2float(hb[(r + 2) * HROW + c0 + j]);
                oc[j] = fmaf(w0[j], lv, fmaf(w1[j], cv, fmaf(w2[j], rv, bb[j])));
            }
            __half2* dst = (__half2*)(g_mixed + (size_t)m * DIMn + c0);
            dst[0] = __floats2half2_rn(oc[0], oc[1]);
            dst[1] = __floats2half2_rn(oc[2], oc[3]);
        }
        return;
    }

    int bid = blockIdx.x - 1024;
    if (bid >= 4096) {
        // ---------- bias pack ----------
        const int i = (bid - 4096) * 256 + t;
        if (i < NBIG) {
            float v;
            if (i < 1024)      v = bi[i];
            else if (i < 2048) v = bg[i - 1024];
            else if (i < 2304) v = bsin[i - 2048];
            else if (i < 2560) v = bd[i - 2304];
            else               v = bsel[i - 2560];
            g_bias[i] = v;
        }
        return;
    }

    // ---------- weight transpose ----------
    float (*tile)[33] = (float(*)[33])sbuf;   // 32x33 floats = 4224 B
    const float* src; __half* dst; int N, Kd;
    if (bid < 1024)      { src = Wi;   dst = g_wT + OFFB_WI;   N = 1024; Kd = 1024; }
    else if (bid < 2048) { src = Wg;   dst = g_wT + OFFB_WG;   N = 1024; Kd = 1024; bid -= 1024; }
    else if (bid < 2304) { src = Wsin; dst = g_wT + OFFB_WSIN; N = 256;  Kd = 1024; bid -= 2048; }
    else if (bid < 2560) { src = Wd;   dst = g_wT + OFFB_WD;   N = 256;  Kd = 1024; bid -= 2304; }
    else if (bid < 2816) { src = Wsel; dst = g_wT + OFFB_WSEL; N = 256;  Kd = 1024; bid -= 2560; }
    else if (bid < 3072) { src = Wso;  dst = g_wT + OFF_WSO;   N = 1024; Kd = 256;  bid -= 2816; }
    else                 { src = Wout; dst = g_wT + OFF_WOUT;  N = 1024; Kd = 1024; bid -= 3072; }
    const int ntx = N / 32;
    const int n0 = (bid % ntx) * 32, k0 = (bid / ntx) * 32;
    const int tx = t & 31, ty = t >> 5;
    #pragma unroll
    for (int j = 0; j < 32; j += 8)
        tile[ty + j][tx] = src[(size_t)(k0 + ty + j) * N + n0 + tx];
    __syncthreads();
    #pragma unroll
    for (int j = 0; j < 32; j += 8)
        dst[(size_t)(n0 + ty + j) * Kd + k0 + tx] = __float2half_rn(tile[tx][ty + j]);
}

// ---------------- chunked scan, TCH=32, 256 threads (round-12 proven) -----
__global__ void scan_p1() {
    const int b = blockIdx.y, c = blockIdx.x, n = threadIdx.x;
    const size_t base = (size_t)(b * Sn + c * TCH) * SDIMn + n;
    float A = 1.f, st = 0.f;
    #pragma unroll
    for (int t = 0; t < TCH; t++) {
        const float d  = g_dec[base + (size_t)t * SDIMn];
        const float xv = g_xs [base + (size_t)t * SDIMn];
        A *= d;
        st = fmaf(d, st, (1.f - d) * xv);
    }
    const int o = (b * NCH + c) * SDIMn + n;
    g_chA[o] = A; g_chB[o] = st;
}
__global__ void scan_p2() {
    const int b = blockIdx.x, n = threadIdx.x;
    float s = 0.f;
    #pragma unroll 4
    for (int c = 0; c < NCH; c++) {
        const int o = (b * NCH + c) * SDIMn + n;
        g_chS0[o] = s;
        s = fmaf(g_chA[o], s, g_chB[o]);
    }
}
__global__ void scan_p3() {
    const int b = blockIdx.y, c = blockIdx.x, n = threadIdx.x;
    const size_t base = (size_t)(b * Sn + c * TCH) * SDIMn + n;
    float st = g_chS0[(b * NCH + c) * SDIMn + n];
    #pragma unroll
    for (int t = 0; t < TCH; t++) {
        const float d  = g_dec[base + (size_t)t * SDIMn];
        const float xv = g_xs [base + (size_t)t * SDIMn];
        st = fmaf(d, st, (1.f - d) * xv);
        const float sl = __half2float(g_sel[base + (size_t)t * SDIMn]);
        g_st[base + (size_t)t * SDIMn] = __float2half_rn(sl * st);
    }
}

// ---------------- fp16 mma GEMM: 128x128 tile, K-chunk 64, 3-stage ring ---
constexpr int HPAD   = 72;                    // halves per smem row (64 + 8 pad)
constexpr int ROWB   = HPAD * 2;              // 144 bytes
constexpr int SROWS  = 256;                   // A rows 0-127, B rows 128-255
constexpr int STG_B  = SROWS * ROWB;          // 36864 B
constexpr int STAGES = 3;
constexpr int GSMEM  = STAGES * STG_B;        // 110592 B per CTA

template <int EPI, int K>
__global__ void __launch_bounds__(256, 2)
mma3(const __half* __restrict__ A, const __half* __restrict__ Bt,
     const float* __restrict__ bias, void* __restrict__ Cv,
     const void* __restrict__ e1, const void* __restrict__ e2,
     int ldc, int lde) {
    extern __shared__ __half smh[];
    const int tid  = threadIdx.x;
    const int wid  = tid >> 5, lane = tid & 31;
    const int wm   = wid & 1;        // 2 row groups of 64
    const int wn   = wid >> 1;       // 4 col groups of 32
    const int bm   = blockIdx.y * 128;
    const int bn   = blockIdx.x * 128;
    const uint32_t base = smem_u32(smh);
    uint32_t sbase[STAGES];
    #pragma unroll
    for (int s = 0; s < STAGES; s++) sbase[s] = base + (uint32_t)(s * STG_B);

    const int r0 = tid >> 3;
    const int q  = tid & 7;
    const __half* nA = A  + (size_t)(bm + r0) * K + q * 8;
    const __half* nB = Bt + (size_t)(bn + r0) * K + q * 8;
    uint32_t swoff[8];
    #pragma unroll
    for (int i = 0; i < 8; i++)
        swoff[i] = (uint32_t)((i * 32 + r0) * ROWB + q * 16);

    auto stage = [&](int buf) {
        const uint32_t sb = sbase[buf];
        #pragma unroll
        for (int i = 0; i < 4; i++)
            cpa16(sb + swoff[i], nA + (size_t)i * 32 * K);
        #pragma unroll
        for (int i = 0; i < 4; i++)
            cpa16(sb + swoff[4 + i], nB + (size_t)i * 32 * K);
        asm volatile("cp.async.commit_group;" ::: "memory");
        nA += 64; nB += 64;
    };

    uint32_t offA[4], offB[2];
    {
        const int blk = lane >> 3, rIn = lane & 7;
        #pragma unroll
        for (int i = 0; i < 4; i++) {
            const int row = wm * 64 + 16 * i + (blk & 1) * 8 + rIn;
            const int kh  = (blk >> 1) * 8;
            offA[i] = (uint32_t)(row * ROWB + kh * 2);
        }
        #pragma unroll
        for (int p = 0; p < 2; p++) {
            const int row = 128 + wn * 32 + 16 * p + (blk >> 1) * 8 + rIn;
            const int kh  = (blk & 1) * 8;
            offB[p] = (uint32_t)(row * ROWB + kh * 2);
        }
    }

    float acc[4][4][4];
    #pragma unroll
    for (int i = 0; i < 4; i++)
        #pragma unroll
        for (int j = 0; j < 4; j++)
            #pragma unroll
            for (int qq = 0; qq < 4; qq++) acc[i][j][qq] = 0.f;

    constexpr int NKS = K / 64;
    static_assert(NKS >= 2, "K too small");

    stage(0);
    stage(1);

    int buf = 0;
    for (int ks = 0; ks < NKS; ks++) {
        asm volatile("cp.async.wait_group %0;" :: "n"(STAGES - 2) : "memory");
        __syncthreads();

        if (ks + STAGES - 1 < NKS) {
            int slot = buf + (STAGES - 1);
            if (slot >= STAGES) slot -= STAGES;
            stage(slot);
        } else {
            asm volatile("cp.async.commit_group;" ::: "memory");
        }

        const uint32_t sb = sbase[buf];
        #pragma unroll
        for (int k0 = 0; k0 < 4; k0++) {
            const uint32_t kb = sb + (uint32_t)(k0 * 32);
            uint32_t afr[4][4], bfr[4][2];
            #pragma unroll
            for (int i = 0; i < 4; i++) ldsm4(afr[i], kb + offA[i]);
            #pragma unroll
            for (int p = 0; p < 2; p++) {
                uint32_t r[4];
                ldsm4(r, kb + offB[p]);
                bfr[2 * p][0] = r[0];     bfr[2 * p][1] = r[1];
                bfr[2 * p + 1][0] = r[2]; bfr[2 * p + 1][1] = r[3];
            }
            #pragma unroll
            for (int i = 0; i < 4; i++)
                #pragma unroll
                for (int j = 0; j < 4; j++)
                    mma16(acc[i][j], afr[i], bfr[j]);
        }
        if (++buf == STAGES) buf = 0;
    }

    // ---- epilogue ----
    __half* dsth = nullptr; float* dstf = nullptr;
    int ldd = 0, cbase = 0;
    bool useTanh = false;
    if (EPI == 0) {
        if (bn < COL_G)        { dsth = g_u;    ldd = 1024;  cbase = 0;       useTanh = true;  }
        else if (bn < COL_XS)  { dsth = g_gate; ldd = 1024;  cbase = COL_G;   useTanh = false; }
        else if (bn < COL_DEC) { dstf = g_xs;   ldd = SDIMn; cbase = COL_XS;  useTanh = true;  }
        else if (bn < COL_SEL) { dstf = g_dec;  ldd = SDIMn; cbase = COL_DEC; useTanh = false; }
        else                   { dsth = g_sel;  ldd = SDIMn; cbase = COL_SEL; useTanh = false; }
    }
    const int g  = lane >> 2, tg = lane & 3;
    #pragma unroll
    for (int i = 0; i < 4; i++) {
        const int rr0 = bm + wm * 64 + 16 * i + g;
        #pragma unroll
        for (int j = 0; j < 4; j++) {
            const int col = bn + wn * 32 + 8 * j + 2 * tg;
            const float2 bs = *(const float2*)(bias + col);
            #pragma unroll
            for (int h = 0; h < 2; h++) {
                const int row = rr0 + 8 * h;
                const float v0 = acc[i][j][2 * h]     + bs.x;
                const float v1 = acc[i][j][2 * h + 1] + bs.y;
                if (EPI == 0) {
                    const int cl = col - cbase;
                    if (dsth) {
                        // fp16-stored: fast approx activations
                        float a0, a1;
                        if (useTanh) { a0 = tanh_fast(v0); a1 = tanh_fast(v1); }
                        else         { a0 = sig_fast(v0);  a1 = sig_fast(v1);  }
                        *(__half2*)(dsth + (size_t)row * ldd + cl) =
                            __floats2half2_rn(a0, a1);
                    } else {
                        // fp32-stored (feeds the scan): exact activations
                        float a0, a1;
                        if (useTanh) { a0 = tanhf(v0); a1 = tanhf(v1); }
                        else {
                            a0 = 1.f / (1.f + expf(-v0));
                            a1 = 1.f / (1.f + expf(-v1));
                        }
                        float2 o; o.x = a0; o.y = a1;
                        *(float2*)(dstf + (size_t)row * ldd + cl) = o;
                    }
                } else if (EPI == 1) {
                    const __half2 gg2 = *(const __half2*)((const __half*)e1 +
                                          (size_t)row * lde + col);
                    const __half2 uu2 = *(const __half2*)((const __half*)e2 +
                                          (size_t)row * lde + col);
                    const float gx = __low2float(gg2), gy = __high2float(gg2);
                    const float ux = __low2float(uu2), uy = __high2float(uu2);
                    const float z0 = gx * v0 + (1.f - gx) * ux;
                    const float z1 = gy * v1 + (1.f - gy) * uy;
                    *(__half2*)((__half*)Cv + (size_t)row * ldc + col) =
                        __floats2half2_rn(z0, z1);
                } else {
                    const float2 xx = *(const float2*)((const float*)e1 +
                                        (size_t)row * lde + col);
                    float2 o;
                    o.x = v0 + xx.x;
                    o.y = v1 + xx.y;
                    *(float2*)((float*)Cv + (size_t)row * ldc + col) = o;
                }
            }
        }
    }
}

// ---------------- launcher ----------------
extern "C" void kernel_launch(void* const* d_in, const int* in_sizes, int n_in,
                              void* d_out, int out_size) {
    const float* x    = (const float*)d_in[0];
    const float* ln_g = (const float*)d_in[1];
    const float* ln_b = (const float*)d_in[2];
    const float* mixw = (const float*)d_in[3];
    const float* mixb = (const float*)d_in[4];
    const float* Wi   = (const float*)d_in[5];
    const float* bi   = (const float*)d_in[6];
    const float* Wsin = (const float*)d_in[7];
    const float* bsin = (const float*)d_in[8];
    const float* Wd   = (const float*)d_in[9];
    const float* bd   = (const float*)d_in[10];
    const float* Wsel = (const float*)d_in[11];
    const float* bsel = (const float*)d_in[12];
    const float* Wso  = (const float*)d_in[13];
    const float* bso  = (const float*)d_in[14];
    const float* Wg   = (const float*)d_in[15];
    const float* bg   = (const float*)d_in[16];
    const float* Wout = (const float*)d_in[17];
    const float* bout = (const float*)d_in[18];

    float *p_bias;
    __half *p_mixed, *p_st, *p_z, *p_wT, *p_gate, *p_u;
    cudaGetSymbolAddress((void**)&p_mixed, g_mixed);
    cudaGetSymbolAddress((void**)&p_st,    g_st);
    cudaGetSymbolAddress((void**)&p_z,     g_z);
    cudaGetSymbolAddress((void**)&p_wT,    g_wT);
    cudaGetSymbolAddress((void**)&p_bias,  g_bias);
    cudaGetSymbolAddress((void**)&p_gate,  g_gate);
    cudaGetSymbolAddress((void**)&p_u,     g_u);

    cudaFuncSetAttribute((const void*)mma3<0, 1024>,
                         cudaFuncAttributeMaxDynamicSharedMemorySize, GSMEM);
    cudaFuncSetAttribute((const void*)mma3<1, 256>,
                         cudaFuncAttributeMaxDynamicSharedMemorySize, GSMEM);
    cudaFuncSetAttribute((const void*)mma3<2, 1024>,
                         cudaFuncAttributeMaxDynamicSharedMemorySize, GSMEM);

    // launch 0: merged LN+conv / transposes / bias pack
    prep_kernel<<<1024 + 4096 + 11, 256>>>(
        x, ln_g, ln_b, mixw, mixb,
        Wi, Wg, Wsin, Wd, Wsel, Wso, Wout,
        bi, bg, bsin, bd, bsel);

    // launch 1: fused projection GEMM -> split activation buffers
    mma3<0, 1024><<<dim3(NBIG / 128, Mn / 128), 256, GSMEM>>>(
        p_mixed, p_wT, p_bias, nullptr, nullptr, nullptr, 0, 0);

    // launch 2-4: chunked scan (TCH=32, 256 threads); p3 writes half(sel*state)
    scan_p1<<<dim3(NCH, Bn), SDIMn>>>();
    scan_p2<<<Bn, SDIMn>>>();
    scan_p3<<<dim3(NCH, Bn), SDIMn>>>();

    // launch 5: y = (sel*st)@Wso + bso, fused gate -> z (fp16)
    mma3<1, 256><<<dim3(DIMn / 128, Mn / 128), 256, GSMEM>>>(
        p_st, p_wT + OFF_WSO, bso, p_z, p_gate, p_u, DIMn, DIMn);

    // launch 6: out = z@Wout + bout + x
    mma3<2, 1024><<<dim3(DIMn / 128, Mn / 128), 256, GSMEM>>>(
        p_z, p_wT + OFF_WOUT, bout, d_out, x, nullptr, DIMn, DIMn);
}